// round 12
// baseline (speedup 1.0000x reference)
#include <cuda_runtime.h>
#include <cuda_fp16.h>

#define NROWS 100000
#define D 128
#define KN 16

// Scratch (no allocations allowed).
__device__ __half g_hidh[NROWS * D];   // fp16 GEMM output (gather source)
__device__ __half g_h1h[NROWS * D];    // fp16 layer-1 activation (layer-2 input)
__device__ float  g_sin[NROWS];
__device__ float  g_sout[NROWS];

// SMEM: W tile 128 rows x 256B at 0; X tile 64 rows x 256B at 32768. 48KB total.
#define WOFF 0
#define XOFF 32768
#define GEMM_SMEM 49152

static __device__ __forceinline__ unsigned pack_h2(float a, float b) {
    __half2 h = __floats2half2_rn(a, b);
    return *(unsigned*)&h;
}

static __device__ __forceinline__ unsigned smem_u32(const void* p) {
    unsigned a;
    asm("{ .reg .u64 t; cvta.to.shared.u64 t, %1; cvt.u32.u64 %0, t; }"
        : "=r"(a) : "l"(p));
    return a;
}

// Load one 16B granule (8 halves) = X[row][g*8 .. g*8+7], converting if fp32.
static __device__ __forceinline__ uint4 load_gran(const float* X, int row, int g) {
    const float4* s = (const float4*)(X + (size_t)row * D + g * 8);
    float4 v0 = s[0], v1 = s[1];
    uint4 h;
    h.x = pack_h2(v0.x, v0.y); h.y = pack_h2(v0.z, v0.w);
    h.z = pack_h2(v1.x, v1.y); h.w = pack_h2(v1.z, v1.w);
    return h;
}
static __device__ __forceinline__ uint4 load_gran(const __half* X, int row, int g) {
    return ((const uint4*)(X + (size_t)row * D))[g];
}

static __device__ __forceinline__ void ldsm_x4(unsigned* r, unsigned addr) {
    asm volatile("ldmatrix.sync.aligned.m8n8.x4.shared.b16 {%0,%1,%2,%3}, [%4];"
        : "=r"(r[0]), "=r"(r[1]), "=r"(r[2]), "=r"(r[3]) : "r"(addr));
}
static __device__ __forceinline__ void ldsm_x2t(unsigned* r, unsigned addr) {
    asm volatile("ldmatrix.sync.aligned.m8n8.x2.trans.shared.b16 {%0,%1}, [%2];"
        : "=r"(r[0]), "=r"(r[1]) : "r"(addr));
}
static __device__ __forceinline__ void mma_f16(
    float& c0, float& c1, float& c2, float& c3,
    unsigned a0, unsigned a1, unsigned a2, unsigned a3,
    unsigned b0, unsigned b1) {
    asm volatile(
        "mma.sync.aligned.m16n8k16.row.col.f32.f16.f16.f32 "
        "{%0,%1,%2,%3}, {%4,%5,%6,%7}, {%8,%9}, {%0,%1,%2,%3};"
        : "+f"(c0), "+f"(c1), "+f"(c2), "+f"(c3)
        : "r"(a0), "r"(a1), "r"(a2), "r"(a3), "r"(b0), "r"(b1));
}

// ---------------------------------------------------------------------------
// fp16 tensor-core GEMM + fused attention-score dots. (unchanged from R10)
// ---------------------------------------------------------------------------
template <typename InT>
__global__ __launch_bounds__(128, 4) void gemm_fused_k(
    const InT* __restrict__ X, const float* __restrict__ W,
    const float* __restrict__ a_in, const float* __restrict__ a_out,
    __half* __restrict__ hidh, float* __restrict__ sin_, float* __restrict__ sout_) {
    extern __shared__ __align__(16) unsigned char smem[];
    const unsigned smem_u = smem_u32(smem);

    const int tx = threadIdx.x;
    const int row0 = blockIdx.x * 64;
    const int wid = tx >> 5, lane = tx & 31;

    // Stage W: 2048 granules, 16 per thread.
#pragma unroll
    for (int it = 0; it < 16; it++) {
        int gi = it * 128 + tx;
        int r = gi >> 4, g = gi & 15;
        uint4 h = load_gran(W, r, g);
        *(uint4*)(smem + WOFF + r * 256 + ((g ^ (r & 7)) << 4)) = h;
    }
    // Stage X tile: 1024 granules, 8 per thread; zero-pad rows >= N.
#pragma unroll
    for (int it = 0; it < 8; it++) {
        int gi = it * 128 + tx;
        int r = gi >> 4, g = gi & 15;
        uint4 h = make_uint4(0u, 0u, 0u, 0u);
        if (row0 + r < NROWS) h = load_gran(X, row0 + r, g);
        *(uint4*)(smem + XOFF + r * 256 + ((g ^ (r & 7)) << 4)) = h;
    }
    __syncthreads();

    const int l15 = lane & 15;
    const int aRow = (lane & 7) + ((lane >> 3) & 1) * 8;
    const int aGsel = lane >> 4;
    const int aR7 = aRow & 7;
    unsigned bBase[4];
#pragma unroll
    for (int nt = 0; nt < 4; nt++)
        bBase[nt] = smem_u + WOFF + l15 * 256 + (((wid * 4 + nt) ^ (l15 & 7)) << 4);
    const unsigned aBase = smem_u + XOFF + aRow * 256;

    float c[4][4][4];
#pragma unroll
    for (int mt = 0; mt < 4; mt++)
#pragma unroll
        for (int nt = 0; nt < 4; nt++)
#pragma unroll
            for (int j = 0; j < 4; j++) c[mt][nt][j] = 0.f;

#pragma unroll
    for (int k0 = 0; k0 < D; k0 += 16) {
        const int kg = k0 >> 3;
        const unsigned ag = (unsigned)(((kg + aGsel) ^ aR7) << 4);
        unsigned a[4][4], b[4][2];
#pragma unroll
        for (int mt = 0; mt < 4; mt++)
            ldsm_x4(a[mt], aBase + mt * 4096 + ag);
#pragma unroll
        for (int nt = 0; nt < 4; nt++)
            ldsm_x2t(b[nt], bBase[nt] + k0 * 256);
#pragma unroll
        for (int mt = 0; mt < 4; mt++)
#pragma unroll
            for (int nt = 0; nt < 4; nt++)
                mma_f16(c[mt][nt][0], c[mt][nt][1], c[mt][nt][2], c[mt][nt][3],
                        a[mt][0], a[mt][1], a[mt][2], a[mt][3],
                        b[nt][0], b[nt][1]);
    }

    // ---- Score dots (fp32): per-warp partials -> SMEM -> cross-warp sum ----
    const int lane4 = lane & 3, laneD4 = lane >> 2;
    float ai0[4], ai1[4], ao0[4], ao1[4];
#pragma unroll
    for (int nt = 0; nt < 4; nt++) {
        int cb = wid * 32 + nt * 8 + lane4 * 2;
        ai0[nt] = a_in[cb];  ai1[nt] = a_in[cb + 1];
        ao0[nt] = a_out[cb]; ao1[nt] = a_out[cb + 1];
    }

    __syncthreads();
    float* red = (float*)(smem + XOFF);    // [2][64 rows][4 warps]

#pragma unroll
    for (int mt = 0; mt < 4; mt++) {
        float si_lo = 0.f, si_hi = 0.f, so_lo = 0.f, so_hi = 0.f;
#pragma unroll
        for (int nt = 0; nt < 4; nt++) {
            si_lo += c[mt][nt][0] * ai0[nt] + c[mt][nt][1] * ai1[nt];
            si_hi += c[mt][nt][2] * ai0[nt] + c[mt][nt][3] * ai1[nt];
            so_lo += c[mt][nt][0] * ao0[nt] + c[mt][nt][1] * ao1[nt];
            so_hi += c[mt][nt][2] * ao0[nt] + c[mt][nt][3] * ao1[nt];
        }
#pragma unroll
        for (int o = 1; o <= 2; o <<= 1) {
            si_lo += __shfl_xor_sync(0xffffffffu, si_lo, o);
            si_hi += __shfl_xor_sync(0xffffffffu, si_hi, o);
            so_lo += __shfl_xor_sync(0xffffffffu, so_lo, o);
            so_hi += __shfl_xor_sync(0xffffffffu, so_hi, o);
        }
        if (lane4 == 0) {
            int rt = mt * 16 + laneD4;
            red[rt * 4 + wid]             = si_lo;
            red[(rt + 8) * 4 + wid]       = si_hi;
            red[256 + rt * 4 + wid]       = so_lo;
            red[256 + (rt + 8) * 4 + wid] = so_hi;
        }
    }
    __syncthreads();
    if (tx < 64 && row0 + tx < NROWS) {
        float si = red[tx * 4] + red[tx * 4 + 1] + red[tx * 4 + 2] + red[tx * 4 + 3];
        float so = red[256 + tx * 4] + red[256 + tx * 4 + 1] +
                   red[256 + tx * 4 + 2] + red[256 + tx * 4 + 3];
        sin_[row0 + tx] = si;
        sout_[row0 + tx] = so;
    }

    // ---- Store hid fragments as fp16 ----
    unsigned* hidh2 = (unsigned*)hidh;
#pragma unroll
    for (int mt = 0; mt < 4; mt++) {
        int r_lo = row0 + mt * 16 + laneD4;
        int r_hi = r_lo + 8;
        if (r_lo < NROWS) {
#pragma unroll
            for (int nt = 0; nt < 4; nt++) {
                int cb = wid * 32 + nt * 8 + lane4 * 2;
                hidh2[(size_t)r_lo * 64 + (cb >> 1)] = pack_h2(c[mt][nt][0], c[mt][nt][1]);
            }
        }
        if (r_hi < NROWS) {
#pragma unroll
            for (int nt = 0; nt < 4; nt++) {
                int cb = wid * 32 + nt * 8 + lane4 * 2;
                hidh2[(size_t)r_hi * 64 + (cb >> 1)] = pack_h2(c[mt][nt][2], c[mt][nt][3]);
            }
        }
    }
}

// ---------------------------------------------------------------------------
// Softmax(K=16) + weighted neighbor aggregation + bias + ReLU.
// One warp per dst row. All 16 gathers are issued as ONE batched wave into a
// uint2[16] register array (forced MLP=16), then a pure FMA accumulate pass.
// ---------------------------------------------------------------------------
template <typename OutT>
__global__ __launch_bounds__(128) void agg_k(
    const __half* __restrict__ hidh, const float* __restrict__ sin_,
    const float* __restrict__ sout_, const int* __restrict__ dst,
    const float* __restrict__ adj, const float* __restrict__ b,
    OutT* __restrict__ out) {
    const int row = blockIdx.x * 4 + (threadIdx.x >> 5);
    const int lane = threadIdx.x & 31;

    int dd = 0;
    float we = 0.f;
    if (lane < KN) {
        dd = dst[row * KN + lane];
        float e = sin_[row] + sout_[dd];
        e = e > 0.f ? e : 0.2f * e;
        float m = e;
#pragma unroll
        for (int o = 8; o; o >>= 1)
            m = fmaxf(m, __shfl_xor_sync(0xffffu, m, o, 16));
        float ex = __expf(e - m);
        float s = ex;
#pragma unroll
        for (int o = 8; o; o >>= 1)
            s += __shfl_xor_sync(0xffffu, s, o, 16);
        we = adj[row * KN + lane] * (ex / s);
    }

    // Broadcast all (dk, wk) pairs up front.
    unsigned dk[KN];
    float wk[KN];
#pragma unroll
    for (int k = 0; k < KN; k++) {
        dk[k] = (unsigned)__shfl_sync(0xffffffffu, dd, k);
        wk[k] = __shfl_sync(0xffffffffu, we, k);
    }

    float4 acc = ((const float4*)b)[lane];   // issued before the gather wave

    // One batched gather wave: 16 independent LDG.64 in flight.
    const uint2* hh = (const uint2*)hidh;
    uint2 v[KN];
#pragma unroll
    for (int k = 0; k < KN; k++)
        v[k] = hh[dk[k] * 32u + (unsigned)lane];

    // Accumulate (fp32).
#pragma unroll
    for (int k = 0; k < KN; k++) {
        float2 f0 = __half22float2(*(const __half2*)&v[k].x);
        float2 f1 = __half22float2(*(const __half2*)&v[k].y);
        acc.x = fmaf(wk[k], f0.x, acc.x);
        acc.y = fmaf(wk[k], f0.y, acc.y);
        acc.z = fmaf(wk[k], f1.x, acc.z);
        acc.w = fmaf(wk[k], f1.y, acc.w);
    }
    acc.x = fmaxf(acc.x, 0.f); acc.y = fmaxf(acc.y, 0.f);
    acc.z = fmaxf(acc.z, 0.f); acc.w = fmaxf(acc.w, 0.f);
    if constexpr (sizeof(OutT) == 2) {
        uint2 p;
        p.x = pack_h2(acc.x, acc.y);
        p.y = pack_h2(acc.z, acc.w);
        ((uint2*)out)[(size_t)row * 32 + lane] = p;
    } else {
        ((float4*)out)[(size_t)row * 32 + lane] = acc;
    }
}

// ---------------------------------------------------------------------------

extern "C" void kernel_launch(void* const* d_in, const int* in_sizes, int n_in,
                              void* d_out, int out_size) {
    const float* x     = (const float*)d_in[0];
    const int*   dst   = (const int*)  d_in[1];
    const float* adj   = (const float*)d_in[2];
    const float* w1    = (const float*)d_in[3];
    const float* ain1  = (const float*)d_in[4];
    const float* aout1 = (const float*)d_in[5];
    const float* b1    = (const float*)d_in[6];
    const float* w2    = (const float*)d_in[7];
    const float* ain2  = (const float*)d_in[8];
    const float* aout2 = (const float*)d_in[9];
    const float* b2    = (const float*)d_in[10];
    float* out = (float*)d_out;

    __half *hidh, *h1h;
    float *sin_, *sout_;
    cudaGetSymbolAddress((void**)&hidh,  g_hidh);
    cudaGetSymbolAddress((void**)&h1h,   g_h1h);
    cudaGetSymbolAddress((void**)&sin_,  g_sin);
    cudaGetSymbolAddress((void**)&sout_, g_sout);

    static bool attr_set = false;
    if (!attr_set) {
        cudaFuncSetAttribute(gemm_fused_k<float>,
                             cudaFuncAttributeMaxDynamicSharedMemorySize, GEMM_SMEM);
        cudaFuncSetAttribute(gemm_fused_k<__half>,
                             cudaFuncAttributeMaxDynamicSharedMemorySize, GEMM_SMEM);
        attr_set = true;
    }

    const int gemm_grid = (NROWS + 63) / 64;   // 1563
    const int agg_grid  = NROWS / 4;           // 25000

    // Layer 1
    gemm_fused_k<float><<<gemm_grid, 128, GEMM_SMEM>>>(x, w1, ain1, aout1, hidh, sin_, sout_);
    agg_k<__half><<<agg_grid, 128>>>(hidh, sin_, sout_, dst, adj, b1, h1h);

    // Layer 2
    gemm_fused_k<__half><<<gemm_grid, 128, GEMM_SMEM>>>(h1h, w2, ain2, aout2, hidh, sin_, sout_);
    agg_k<float><<<agg_grid, 128>>>(hidh, sin_, sout_, dst, adj, b2, out);
}

// round 14
// speedup vs baseline: 1.6171x; 1.6171x over previous
#include <cuda_runtime.h>
#include <cuda_fp16.h>

#define NROWS 100000
#define D 128
#define KN 16

// Scratch (no allocations allowed).
__device__ __half g_hidh[NROWS * D];   // fp16 GEMM output (gather source)
__device__ __half g_h1h[NROWS * D];    // fp16 layer-1 activation (layer-2 input)
__device__ float  g_sin[NROWS];
__device__ float  g_sout[NROWS];

// SMEM: W tile 128 rows x 256B at 0; X tile 64 rows x 256B at 32768. 48KB total.
#define WOFF 0
#define XOFF 32768
#define GEMM_SMEM 49152

static __device__ __forceinline__ unsigned pack_h2(float a, float b) {
    __half2 h = __floats2half2_rn(a, b);
    return *(unsigned*)&h;
}

static __device__ __forceinline__ unsigned smem_u32(const void* p) {
    unsigned a;
    asm("{ .reg .u64 t; cvta.to.shared.u64 t, %1; cvt.u32.u64 %0, t; }"
        : "=r"(a) : "l"(p));
    return a;
}

// Load one 16B granule (8 halves) = X[row][g*8 .. g*8+7], converting if fp32.
static __device__ __forceinline__ uint4 load_gran(const float* X, int row, int g) {
    const float4* s = (const float4*)(X + (size_t)row * D + g * 8);
    float4 v0 = s[0], v1 = s[1];
    uint4 h;
    h.x = pack_h2(v0.x, v0.y); h.y = pack_h2(v0.z, v0.w);
    h.z = pack_h2(v1.x, v1.y); h.w = pack_h2(v1.z, v1.w);
    return h;
}
static __device__ __forceinline__ uint4 load_gran(const __half* X, int row, int g) {
    return ((const uint4*)(X + (size_t)row * D))[g];
}

static __device__ __forceinline__ void ldsm_x4(unsigned* r, unsigned addr) {
    asm volatile("ldmatrix.sync.aligned.m8n8.x4.shared.b16 {%0,%1,%2,%3}, [%4];"
        : "=r"(r[0]), "=r"(r[1]), "=r"(r[2]), "=r"(r[3]) : "r"(addr));
}
static __device__ __forceinline__ void ldsm_x2t(unsigned* r, unsigned addr) {
    asm volatile("ldmatrix.sync.aligned.m8n8.x2.trans.shared.b16 {%0,%1}, [%2];"
        : "=r"(r[0]), "=r"(r[1]) : "r"(addr));
}
static __device__ __forceinline__ void mma_f16(
    float& c0, float& c1, float& c2, float& c3,
    unsigned a0, unsigned a1, unsigned a2, unsigned a3,
    unsigned b0, unsigned b1) {
    asm volatile(
        "mma.sync.aligned.m16n8k16.row.col.f32.f16.f16.f32 "
        "{%0,%1,%2,%3}, {%4,%5,%6,%7}, {%8,%9}, {%0,%1,%2,%3};"
        : "+f"(c0), "+f"(c1), "+f"(c2), "+f"(c3)
        : "r"(a0), "r"(a1), "r"(a2), "r"(a3), "r"(b0), "r"(b1));
}

// cp.async.cg: 16 bytes per lane (the only size .cg supports).
static __device__ __forceinline__ void cpasync16(unsigned saddr, const void* gaddr) {
    asm volatile("cp.async.cg.shared.global [%0], [%1], 16;"
        :: "r"(saddr), "l"(gaddr));
}

// ---------------------------------------------------------------------------
// fp16 tensor-core GEMM + fused attention-score dots. (unchanged from R10)
// ---------------------------------------------------------------------------
template <typename InT>
__global__ __launch_bounds__(128, 4) void gemm_fused_k(
    const InT* __restrict__ X, const float* __restrict__ W,
    const float* __restrict__ a_in, const float* __restrict__ a_out,
    __half* __restrict__ hidh, float* __restrict__ sin_, float* __restrict__ sout_) {
    extern __shared__ __align__(16) unsigned char smem[];
    const unsigned smem_u = smem_u32(smem);

    const int tx = threadIdx.x;
    const int row0 = blockIdx.x * 64;
    const int wid = tx >> 5, lane = tx & 31;

    // Stage W: 2048 granules, 16 per thread.
#pragma unroll
    for (int it = 0; it < 16; it++) {
        int gi = it * 128 + tx;
        int r = gi >> 4, g = gi & 15;
        uint4 h = load_gran(W, r, g);
        *(uint4*)(smem + WOFF + r * 256 + ((g ^ (r & 7)) << 4)) = h;
    }
    // Stage X tile: 1024 granules, 8 per thread; zero-pad rows >= N.
#pragma unroll
    for (int it = 0; it < 8; it++) {
        int gi = it * 128 + tx;
        int r = gi >> 4, g = gi & 15;
        uint4 h = make_uint4(0u, 0u, 0u, 0u);
        if (row0 + r < NROWS) h = load_gran(X, row0 + r, g);
        *(uint4*)(smem + XOFF + r * 256 + ((g ^ (r & 7)) << 4)) = h;
    }
    __syncthreads();

    const int l15 = lane & 15;
    const int aRow = (lane & 7) + ((lane >> 3) & 1) * 8;
    const int aGsel = lane >> 4;
    const int aR7 = aRow & 7;
    unsigned bBase[4];
#pragma unroll
    for (int nt = 0; nt < 4; nt++)
        bBase[nt] = smem_u + WOFF + l15 * 256 + (((wid * 4 + nt) ^ (l15 & 7)) << 4);
    const unsigned aBase = smem_u + XOFF + aRow * 256;

    float c[4][4][4];
#pragma unroll
    for (int mt = 0; mt < 4; mt++)
#pragma unroll
        for (int nt = 0; nt < 4; nt++)
#pragma unroll
            for (int j = 0; j < 4; j++) c[mt][nt][j] = 0.f;

#pragma unroll
    for (int k0 = 0; k0 < D; k0 += 16) {
        const int kg = k0 >> 3;
        const unsigned ag = (unsigned)(((kg + aGsel) ^ aR7) << 4);
        unsigned a[4][4], b[4][2];
#pragma unroll
        for (int mt = 0; mt < 4; mt++)
            ldsm_x4(a[mt], aBase + mt * 4096 + ag);
#pragma unroll
        for (int nt = 0; nt < 4; nt++)
            ldsm_x2t(b[nt], bBase[nt] + k0 * 256);
#pragma unroll
        for (int mt = 0; mt < 4; mt++)
#pragma unroll
            for (int nt = 0; nt < 4; nt++)
                mma_f16(c[mt][nt][0], c[mt][nt][1], c[mt][nt][2], c[mt][nt][3],
                        a[mt][0], a[mt][1], a[mt][2], a[mt][3],
                        b[nt][0], b[nt][1]);
    }

    // ---- Score dots (fp32): per-warp partials -> SMEM -> cross-warp sum ----
    const int lane4 = lane & 3, laneD4 = lane >> 2;
    float ai0[4], ai1[4], ao0[4], ao1[4];
#pragma unroll
    for (int nt = 0; nt < 4; nt++) {
        int cb = wid * 32 + nt * 8 + lane4 * 2;
        ai0[nt] = a_in[cb];  ai1[nt] = a_in[cb + 1];
        ao0[nt] = a_out[cb]; ao1[nt] = a_out[cb + 1];
    }

    __syncthreads();
    float* red = (float*)(smem + XOFF);    // [2][64 rows][4 warps]

#pragma unroll
    for (int mt = 0; mt < 4; mt++) {
        float si_lo = 0.f, si_hi = 0.f, so_lo = 0.f, so_hi = 0.f;
#pragma unroll
        for (int nt = 0; nt < 4; nt++) {
            si_lo += c[mt][nt][0] * ai0[nt] + c[mt][nt][1] * ai1[nt];
            si_hi += c[mt][nt][2] * ai0[nt] + c[mt][nt][3] * ai1[nt];
            so_lo += c[mt][nt][0] * ao0[nt] + c[mt][nt][1] * ao1[nt];
            so_hi += c[mt][nt][2] * ao0[nt] + c[mt][nt][3] * ao1[nt];
        }
#pragma unroll
        for (int o = 1; o <= 2; o <<= 1) {
            si_lo += __shfl_xor_sync(0xffffffffu, si_lo, o);
            si_hi += __shfl_xor_sync(0xffffffffu, si_hi, o);
            so_lo += __shfl_xor_sync(0xffffffffu, so_lo, o);
            so_hi += __shfl_xor_sync(0xffffffffu, so_hi, o);
        }
        if (lane4 == 0) {
            int rt = mt * 16 + laneD4;
            red[rt * 4 + wid]             = si_lo;
            red[(rt + 8) * 4 + wid]       = si_hi;
            red[256 + rt * 4 + wid]       = so_lo;
            red[256 + (rt + 8) * 4 + wid] = so_hi;
        }
    }
    __syncthreads();
    if (tx < 64 && row0 + tx < NROWS) {
        float si = red[tx * 4] + red[tx * 4 + 1] + red[tx * 4 + 2] + red[tx * 4 + 3];
        float so = red[256 + tx * 4] + red[256 + tx * 4 + 1] +
                   red[256 + tx * 4 + 2] + red[256 + tx * 4 + 3];
        sin_[row0 + tx] = si;
        sout_[row0 + tx] = so;
    }

    // ---- Store hid fragments as fp16 ----
    unsigned* hidh2 = (unsigned*)hidh;
#pragma unroll
    for (int mt = 0; mt < 4; mt++) {
        int r_lo = row0 + mt * 16 + laneD4;
        int r_hi = r_lo + 8;
        if (r_lo < NROWS) {
#pragma unroll
            for (int nt = 0; nt < 4; nt++) {
                int cb = wid * 32 + nt * 8 + lane4 * 2;
                hidh2[(size_t)r_lo * 64 + (cb >> 1)] = pack_h2(c[mt][nt][0], c[mt][nt][1]);
            }
        }
        if (r_hi < NROWS) {
#pragma unroll
            for (int nt = 0; nt < 4; nt++) {
                int cb = wid * 32 + nt * 8 + lane4 * 2;
                hidh2[(size_t)r_hi * 64 + (cb >> 1)] = pack_h2(c[mt][nt][2], c[mt][nt][3]);
            }
        }
    }
}

// ---------------------------------------------------------------------------
// Softmax(K=16) + weighted aggregation + bias + ReLU.
// One warp per dst row. Gathers staged via cp.async.cg (16B/lane; 16 lanes
// cover one 256B row, so 2 rows per step x 8 steps = 16 rows all in flight,
// zero data-register cost), then a conflict-free LDS.64 accumulate pass.
// ---------------------------------------------------------------------------
template <typename OutT>
__global__ __launch_bounds__(128) void agg_k(
    const __half* __restrict__ hidh, const float* __restrict__ sin_,
    const float* __restrict__ sout_, const int* __restrict__ dst,
    const float* __restrict__ adj, const float* __restrict__ b,
    OutT* __restrict__ out) {
    __shared__ __align__(16) unsigned char buf[4 * KN * 256];  // 16KB
    const int wid = threadIdx.x >> 5;
    const int row = blockIdx.x * 4 + wid;
    const int lane = threadIdx.x & 31;

    int dd = 0;
    float we = 0.f;
    if (lane < KN) {
        dd = dst[row * KN + lane];
        float e = sin_[row] + sout_[dd];
        e = e > 0.f ? e : 0.2f * e;
        float m = e;
#pragma unroll
        for (int o = 8; o; o >>= 1)
            m = fmaxf(m, __shfl_xor_sync(0xffffu, m, o, 16));
        float ex = __expf(e - m);
        float s = ex;
#pragma unroll
        for (int o = 8; o; o >>= 1)
            s += __shfl_xor_sync(0xffffu, s, o, 16);
        we = adj[row * KN + lane] * (ex / s);
    }

    // Issue all 16 row-gathers: 2 rows per step (16 lanes x 16B each).
    const unsigned swarp = smem_u32(buf) + wid * (KN * 256);
    const int rsel = lane >> 4;           // 0 or 1: which row of the pair
    const int loff = (lane & 15) * 16;    // byte offset within the row
#pragma unroll
    for (int k = 0; k < KN; k += 2) {
        unsigned dk = (unsigned)__shfl_sync(0xffffffffu, dd, k + rsel);
        cpasync16(swarp + (k + rsel) * 256 + loff,
                  (const char*)hidh + (size_t)dk * 256 + loff);
    }
    asm volatile("cp.async.commit_group;" ::: "memory");

    float4 acc = ((const float4*)b)[lane];

    asm volatile("cp.async.wait_group 0;" ::: "memory");
    __syncwarp();

    // Accumulate from SMEM (LDS.64, lane-stride 8B: conflict-free 2-phase).
    const unsigned sbase = swarp + lane * 8;
#pragma unroll
    for (int k = 0; k < KN; k++) {
        float wk = __shfl_sync(0xffffffffu, we, k);
        uint2 v;
        asm("ld.shared.v2.u32 {%0, %1}, [%2];"
            : "=r"(v.x), "=r"(v.y) : "r"(sbase + k * 256));
        float2 f0 = __half22float2(*(const __half2*)&v.x);
        float2 f1 = __half22float2(*(const __half2*)&v.y);
        acc.x = fmaf(wk, f0.x, acc.x);
        acc.y = fmaf(wk, f0.y, acc.y);
        acc.z = fmaf(wk, f1.x, acc.z);
        acc.w = fmaf(wk, f1.y, acc.w);
    }
    acc.x = fmaxf(acc.x, 0.f); acc.y = fmaxf(acc.y, 0.f);
    acc.z = fmaxf(acc.z, 0.f); acc.w = fmaxf(acc.w, 0.f);
    if constexpr (sizeof(OutT) == 2) {
        uint2 p;
        p.x = pack_h2(acc.x, acc.y);
        p.y = pack_h2(acc.z, acc.w);
        ((uint2*)out)[(size_t)row * 32 + lane] = p;
    } else {
        ((float4*)out)[(size_t)row * 32 + lane] = acc;
    }
}

// ---------------------------------------------------------------------------

extern "C" void kernel_launch(void* const* d_in, const int* in_sizes, int n_in,
                              void* d_out, int out_size) {
    const float* x     = (const float*)d_in[0];
    const int*   dst   = (const int*)  d_in[1];
    const float* adj   = (const float*)d_in[2];
    const float* w1    = (const float*)d_in[3];
    const float* ain1  = (const float*)d_in[4];
    const float* aout1 = (const float*)d_in[5];
    const float* b1    = (const float*)d_in[6];
    const float* w2    = (const float*)d_in[7];
    const float* ain2  = (const float*)d_in[8];
    const float* aout2 = (const float*)d_in[9];
    const float* b2    = (const float*)d_in[10];
    float* out = (float*)d_out;

    __half *hidh, *h1h;
    float *sin_, *sout_;
    cudaGetSymbolAddress((void**)&hidh,  g_hidh);
    cudaGetSymbolAddress((void**)&h1h,   g_h1h);
    cudaGetSymbolAddress((void**)&sin_,  g_sin);
    cudaGetSymbolAddress((void**)&sout_, g_sout);

    static bool attr_set = false;
    if (!attr_set) {
        cudaFuncSetAttribute(gemm_fused_k<float>,
                             cudaFuncAttributeMaxDynamicSharedMemorySize, GEMM_SMEM);
        cudaFuncSetAttribute(gemm_fused_k<__half>,
                             cudaFuncAttributeMaxDynamicSharedMemorySize, GEMM_SMEM);
        attr_set = true;
    }

    const int gemm_grid = (NROWS + 63) / 64;   // 1563
    const int agg_grid  = NROWS / 4;           // 25000

    // Layer 1
    gemm_fused_k<float><<<gemm_grid, 128, GEMM_SMEM>>>(x, w1, ain1, aout1, hidh, sin_, sout_);
    agg_k<__half><<<agg_grid, 128>>>(hidh, sin_, sout_, dst, adj, b1, h1h);

    // Layer 2
    gemm_fused_k<__half><<<gemm_grid, 128, GEMM_SMEM>>>(h1h, w2, ain2, aout2, hidh, sin_, sout_);
    agg_k<float><<<agg_grid, 128>>>(hidh, sin_, sout_, dst, adj, b2, out);
}